// round 14
// baseline (speedup 1.0000x reference)
#include <cuda_runtime.h>

#define B_ 256
#define T_ 2048
#define S_ 32
#define N_ 19
#define UNF 6
#define CLS 10
#define EPSV 1e-8f
#define LOG2E_ 1.4426950408889634f

// scratch for per-step motor outputs: flat[b][t]  (MOTOR == 1)
__device__ float g_flat[B_ * T_];

__device__ __forceinline__ float ex2f(float x) {
    float y; asm("ex2.approx.ftz.f32 %0, %1;" : "=f"(y) : "f"(x)); return y;
}
__device__ __forceinline__ float rcpf(float x) {
    float y; asm("rcp.approx.ftz.f32 %0, %1;" : "=f"(y) : "f"(x)); return y;
}

// 128 threads = 4 warps = 2 batch "pairs" (2 warps cooperate on one batch).
// Grid = 128 blocks -> 256 batches, ~1 block per SM, 4 warps on 4 SMSPs.
__global__ __launch_bounds__(128, 1)
void ltc_kernel(const float* __restrict__ x,
                const float* __restrict__ input_w, const float* __restrict__ input_b,
                const float* __restrict__ s_mu,   const float* __restrict__ s_sigma,
                const float* __restrict__ s_w,    const float* __restrict__ s_erev,
                const float* __restrict__ mu,     const float* __restrict__ sigma,
                const float* __restrict__ w,      const float* __restrict__ erev,
                const float* __restrict__ gleak,  const float* __restrict__ vleak,
                const float* __restrict__ cm,
                const float* __restrict__ out_w,  const float* __restrict__ out_b,
                const int*   __restrict__ s_mask, const int* __restrict__ mask)
{
    // Folded constants: (A, B, wE, wD) with sig = 1/(1+2^(A*v+B)), contributions wE*sig, wD*sig
    __shared__ float4 cs[S_ * N_];      // sensory, index s*N + n
    __shared__ float4 cr[20 * N_];      // recurrent, index j*N + n ; row j=19 is a zero pad
    __shared__ float2 sp_sens[2][2][20];       // [pair][halfwarp][n]
    __shared__ float2 sp_unf[2][2][2][20];     // [pair][parity][halfwarp][n]

    const int tid  = threadIdx.x;
    const int warp = tid >> 5, lane = tid & 31;
    const int pair = warp >> 1, wp = warp & 1;   // wp: which half of the work
    const int b    = blockIdx.x * 2 + pair;

    // ---- build constant tables (once; 2048-step loop amortizes this) ----
    for (int i = tid; i < S_ * N_; i += 128) {
        float sg = s_sigma[i];
        float wm = s_w[i] * (float)s_mask[i];
        cs[i] = make_float4(-sg * LOG2E_, sg * s_mu[i] * LOG2E_, wm * s_erev[i], wm);
    }
    for (int i = tid; i < 20 * N_; i += 128) {
        if (i < N_ * N_) {
            float sg = sigma[i];
            float wm = w[i] * (float)mask[i];
            cr[i] = make_float4(-sg * LOG2E_, sg * mu[i] * LOG2E_, wm * erev[i], wm);
        } else {
            cr[i] = make_float4(0.f, 0.f, 0.f, 0.f);   // pad row j=19: zero contribution
        }
    }
    __syncthreads();

    const int ln = (lane < N_) ? lane : (N_ - 1);  // clamped column for idle lanes
    float cmt = 0.f, Pc = 0.f, D0 = 0.f;
    if (lane < N_) {
        float gl = gleak[lane];
        cmt = cm[lane] * (float)UNF;               // cm / (dt/unfolds), dt=1
        Pc  = gl * vleak[lane];
        D0  = cmt + gl + EPSV;
    }
    const float ow = out_w[0], ob = out_b[0];
    const float iw = input_w[lane], ib = input_b[lane];

    const int barid = 1 + pair;                    // named barrier per batch-pair (64 threads)
    const float* xb = x + (size_t)b * T_ * S_;

    float inp_next = fmaf(xb[lane], iw, ib);       // prefetch t=0 mapped input (lane = s)
    float v = 0.f;
    const int s0 = wp * 16;                        // sensory split: 16 + 16
    const int j0 = wp * 10;                        // recurrent split: 10 + 10(incl. zero pad)

    for (int t = 0; t < T_; ++t) {
        float inp = inp_next;
        if (t + 1 < T_) inp_next = fmaf(xb[(t + 1) * S_ + lane], iw, ib);  // overlap LDG

        // ---- sensory synapses (half of S per warp), lane = post-neuron ----
        float ns = 0.f, ds = 0.f;
        #pragma unroll
        for (int k = 0; k < 16; ++k) {
            float iv = __shfl_sync(0xffffffffu, inp, s0 + k);
            float4 c = cs[(s0 + k) * N_ + ln];
            float r = rcpf(1.f + ex2f(fmaf(c.x, iv, c.y)));
            ns = fmaf(c.z, r, ns);
            ds = fmaf(c.w, r, ds);
        }
        if (lane < N_) sp_sens[pair][wp][lane] = make_float2(ns, ds);
        asm volatile("bar.sync %0, 64;" :: "r"(barid) : "memory");
        float num_s = 0.f, den_s = 0.f;
        if (lane < N_) {
            float2 o = sp_sens[pair][wp ^ 1][lane];
            num_s = ns + o.x;
            den_s = ds + o.y;
        }

        // ---- 6 ODE unfolds; recurrent synapses split 10/9(+pad) across the pair ----
        #pragma unroll
        for (int u = 0; u < UNF; ++u) {
            float nu = 0.f, du = 0.f;
            #pragma unroll
            for (int k = 0; k < 10; ++k) {
                int j = j0 + k;                                   // j==19 hits zero pad row
                float vj = __shfl_sync(0xffffffffu, v, j & 31);
                float4 c = cr[j * N_ + ln];
                float r = rcpf(1.f + ex2f(fmaf(c.x, vj, c.y)));
                nu = fmaf(c.z, r, nu);
                du = fmaf(c.w, r, du);
            }
            if (lane < N_) sp_unf[pair][u & 1][wp][lane] = make_float2(nu, du);
            asm volatile("bar.sync %0, 64;" :: "r"(barid) : "memory");
            if (lane < N_) {
                float2 o = sp_unf[pair][u & 1][wp ^ 1][lane];
                float wn = nu + o.x + num_s;
                float wd = du + o.y + den_s;
                v = (fmaf(cmt, v, Pc) + wn) * rcpf(D0 + wd);      // both warps compute identically
            }
        }

        // motor output (MOTOR==1): neuron 0 of this batch
        if (wp == 0 && lane == 0)
            g_flat[(size_t)b * T_ + t] = fmaf(v, ow, ob);
    }
}

// Tiny FC over time: out[b][c] = sum_t flat[b][t] * fc_w[c][t] + fc_b[c]
__global__ __launch_bounds__(256)
void fc_kernel(const float* __restrict__ fc_w, const float* __restrict__ fc_b,
               float* __restrict__ out)
{
    const int b = blockIdx.x, tid = threadIdx.x;
    float acc[CLS];
    #pragma unroll
    for (int c = 0; c < CLS; ++c) acc[c] = 0.f;

    const float* fb = g_flat + (size_t)b * T_;
    for (int t = tid; t < T_; t += 256) {
        float f = fb[t];
        #pragma unroll
        for (int c = 0; c < CLS; ++c)
            acc[c] = fmaf(f, fc_w[c * T_ + t], acc[c]);
    }
    // warp reduce
    #pragma unroll
    for (int c = 0; c < CLS; ++c)
        #pragma unroll
        for (int off = 16; off; off >>= 1)
            acc[c] += __shfl_down_sync(0xffffffffu, acc[c], off);

    __shared__ float red[CLS][8];
    const int wid = tid >> 5, lane = tid & 31;
    if (lane == 0) {
        #pragma unroll
        for (int c = 0; c < CLS; ++c) red[c][wid] = acc[c];
    }
    __syncthreads();
    if (tid < CLS) {
        float s = fc_b[tid];
        #pragma unroll
        for (int k = 0; k < 8; ++k) s += red[tid][k];
        out[b * CLS + tid] = s;
    }
}

extern "C" void kernel_launch(void* const* d_in, const int* in_sizes, int n_in,
                              void* d_out, int out_size)
{
    const float* x        = (const float*)d_in[0];
    const float* input_w  = (const float*)d_in[1];
    const float* input_b  = (const float*)d_in[2];
    const float* s_mu     = (const float*)d_in[3];
    const float* s_sigma  = (const float*)d_in[4];
    const float* s_w      = (const float*)d_in[5];
    const float* s_erev   = (const float*)d_in[6];
    const float* mu       = (const float*)d_in[7];
    const float* sigma    = (const float*)d_in[8];
    const float* w        = (const float*)d_in[9];
    const float* erev     = (const float*)d_in[10];
    const float* gleak    = (const float*)d_in[11];
    const float* vleak    = (const float*)d_in[12];
    const float* cm       = (const float*)d_in[13];
    const float* output_w = (const float*)d_in[14];
    const float* output_b = (const float*)d_in[15];
    const float* fc_w     = (const float*)d_in[16];
    const float* fc_b     = (const float*)d_in[17];
    const int*   s_mask   = (const int*)d_in[18];
    const int*   mask     = (const int*)d_in[19];
    float* out = (float*)d_out;

    ltc_kernel<<<B_ / 2, 128>>>(x, input_w, input_b, s_mu, s_sigma, s_w, s_erev,
                                mu, sigma, w, erev, gleak, vleak, cm,
                                output_w, output_b, s_mask, mask);
    fc_kernel<<<B_, 256>>>(fc_w, fc_b, out);
}

// round 15
// speedup vs baseline: 1.1280x; 1.1280x over previous
#include <cuda_runtime.h>

#define B_ 256
#define T_ 2048
#define S_ 32
#define N_ 19
#define UNF 6
#define CLS 10
#define EPSV 1e-8f

// scratch for per-step motor outputs: flat[b][t]  (MOTOR == 1)
__device__ float g_flat[B_ * T_];

__device__ __forceinline__ float tanhf_a(float x) {
    float y; asm("tanh.approx.f32 %0, %1;" : "=f"(y) : "f"(x)); return y;
}
__device__ __forceinline__ float rcpf(float x) {
    float y; asm("rcp.approx.ftz.f32 %0, %1;" : "=f"(y) : "f"(x)); return y;
}

// sigmoid(sg*(v-mu)) = 0.5 + 0.5*tanh(0.5*sg*v - 0.5*sg*mu)
// contribution to num: wE*sig = 0.5*wE + 0.5*wE*tanh(...)
//   -> constant part folded into per-(warp,lane) accumulator init.
// Table entry: (0.5*sg, -0.5*sg*mu, 0.5*wE, 0.5*wD)

// 128 threads = 4 warps = 2 batch "pairs" (2 warps cooperate on one batch).
// Grid = 128 blocks -> ~1 block per SM, each warp alone on its SMSP.
__global__ __launch_bounds__(128, 1)
void ltc_kernel(const float* __restrict__ x,
                const float* __restrict__ input_w, const float* __restrict__ input_b,
                const float* __restrict__ s_mu,   const float* __restrict__ s_sigma,
                const float* __restrict__ s_w,    const float* __restrict__ s_erev,
                const float* __restrict__ mu,     const float* __restrict__ sigma,
                const float* __restrict__ w,      const float* __restrict__ erev,
                const float* __restrict__ gleak,  const float* __restrict__ vleak,
                const float* __restrict__ cm,
                const float* __restrict__ out_w,  const float* __restrict__ out_b,
                const int*   __restrict__ s_mask, const int* __restrict__ mask)
{
    __shared__ float4 cs[S_ * N_];        // sensory tables, index s*N + n
    __shared__ float4 cr[20 * N_];        // recurrent tables, j*N + n ; row 19 = zero pad
    __shared__ float4 sp0[2][2][20];      // merged sensory+unfold0 exchange [pair][wp][n]
    __shared__ float2 spu[2][2][2][20];   // unfold exchange [pair][parity][wp][n]

    const int tid  = threadIdx.x;
    const int warp = tid >> 5, lane = tid & 31;
    const int pair = warp >> 1, wp = warp & 1;
    const int b    = blockIdx.x * 2 + pair;

    // ---- build folded-constant tables (amortized over 2048 steps) ----
    for (int i = tid; i < S_ * N_; i += 128) {
        float sg = s_sigma[i];
        float wm = 0.5f * s_w[i] * (float)s_mask[i];
        cs[i] = make_float4(0.5f * sg, -0.5f * sg * s_mu[i], wm * s_erev[i], wm);
    }
    for (int i = tid; i < 20 * N_; i += 128) {
        if (i < N_ * N_) {
            float sg = sigma[i];
            float wm = 0.5f * w[i] * (float)mask[i];
            cr[i] = make_float4(0.5f * sg, -0.5f * sg * mu[i], wm * erev[i], wm);
        } else {
            cr[i] = make_float4(0.f, 0.f, 0.f, 0.f);
        }
    }
    __syncthreads();

    const int ln = (lane < N_) ? lane : (N_ - 1);
    const int s0 = wp * 16;                 // sensory rows split 16+16
    const int j0 = wp * 10;                 // recurrent rows split 10+10(pad)

    // per-(warp,lane) constant parts of num/den (the 0.5*w terms)
    float Kns = 0.f, Kds = 0.f, Knr = 0.f, Kdr = 0.f;
    #pragma unroll
    for (int k = 0; k < 16; ++k) {
        float4 c = cs[(s0 + k) * N_ + ln];
        Kns += c.z; Kds += c.w;
    }
    #pragma unroll
    for (int k = 0; k < 10; ++k) {
        float4 c = cr[(j0 + k) * N_ + ln];
        Knr += c.z; Kdr += c.w;
    }

    float cmt = 0.f, Pc = 0.f, D0 = 0.f;
    if (lane < N_) {
        float gl = gleak[lane];
        cmt = cm[lane] * (float)UNF;
        Pc  = gl * vleak[lane];
        D0  = cmt + gl + EPSV;
    }
    const float ow = out_w[0], ob = out_b[0];
    const float iw = input_w[lane], ib = input_b[lane];

    const int barid = 1 + pair;             // named barrier per 64-thread batch-pair
    const float* xb = x + (size_t)b * T_ * S_;

    float inp_next = fmaf(xb[lane], iw, ib); // prefetch t=0 (lane = s)
    float v = 0.f;

    for (int t = 0; t < T_; ++t) {
        float inp = inp_next;
        if (t + 1 < T_) inp_next = fmaf(xb[(t + 1) * S_ + lane], iw, ib);

        // ---- sensory partial (16 rows) + unfold-0 recurrent partial (10 rows),
        //      both depend only on previous v -> single merged exchange ----
        float ns = Kns, ds = Kds;
        #pragma unroll
        for (int k = 0; k < 16; ++k) {
            float iv = __shfl_sync(0xffffffffu, inp, s0 + k);
            float4 c = cs[(s0 + k) * N_ + ln];
            float tv = tanhf_a(fmaf(c.x, iv, c.y));
            ns = fmaf(c.z, tv, ns);
            ds = fmaf(c.w, tv, ds);
        }
        float nu = Knr, du = Kdr;
        #pragma unroll
        for (int k = 0; k < 10; ++k) {
            int j = j0 + k;                  // j==19 hits zero pad row
            float vj = __shfl_sync(0xffffffffu, v, j & 31);
            float4 c = cr[j * N_ + ln];
            float tv = tanhf_a(fmaf(c.x, vj, c.y));
            nu = fmaf(c.z, tv, nu);
            du = fmaf(c.w, tv, du);
        }
        if (lane < N_) sp0[pair][wp][lane] = make_float4(ns, ds, nu, du);
        asm volatile("bar.sync %0, 64;" :: "r"(barid) : "memory");

        float num_s = 0.f, den_s = 0.f;
        if (lane < N_) {
            float4 o = sp0[pair][wp ^ 1][lane];
            num_s = ns + o.x;
            den_s = ds + o.y;
            float wn = nu + o.z + num_s;
            float wd = du + o.w + den_s;
            v = (fmaf(cmt, v, Pc) + wn) * rcpf(D0 + wd);   // unfold 0 update
        }

        // ---- unfolds 1..5 ----
        #pragma unroll
        for (int u = 1; u < UNF; ++u) {
            float n2 = Knr, d2 = Kdr;
            #pragma unroll
            for (int k = 0; k < 10; ++k) {
                int j = j0 + k;
                float vj = __shfl_sync(0xffffffffu, v, j & 31);
                float4 c = cr[j * N_ + ln];
                float tv = tanhf_a(fmaf(c.x, vj, c.y));
                n2 = fmaf(c.z, tv, n2);
                d2 = fmaf(c.w, tv, d2);
            }
            if (lane < N_) spu[pair][u & 1][wp][lane] = make_float2(n2, d2);
            asm volatile("bar.sync %0, 64;" :: "r"(barid) : "memory");
            if (lane < N_) {
                float2 o = spu[pair][u & 1][wp ^ 1][lane];
                float wn = n2 + o.x + num_s;
                float wd = d2 + o.y + den_s;
                v = (fmaf(cmt, v, Pc) + wn) * rcpf(D0 + wd);
            }
        }

        if (wp == 0 && lane == 0)
            g_flat[(size_t)b * T_ + t] = fmaf(v, ow, ob);
    }
}

// FC over time: out[b][c] = sum_t flat[b][t] * fc_w[c][t] + fc_b[c]
__global__ __launch_bounds__(256)
void fc_kernel(const float* __restrict__ fc_w, const float* __restrict__ fc_b,
               float* __restrict__ out)
{
    const int b = blockIdx.x, tid = threadIdx.x;
    float acc[CLS];
    #pragma unroll
    for (int c = 0; c < CLS; ++c) acc[c] = 0.f;

    const float* fb = g_flat + (size_t)b * T_;
    for (int t = tid; t < T_; t += 256) {
        float f = fb[t];
        #pragma unroll
        for (int c = 0; c < CLS; ++c)
            acc[c] = fmaf(f, fc_w[c * T_ + t], acc[c]);
    }
    #pragma unroll
    for (int c = 0; c < CLS; ++c)
        #pragma unroll
        for (int off = 16; off; off >>= 1)
            acc[c] += __shfl_down_sync(0xffffffffu, acc[c], off);

    __shared__ float red[CLS][8];
    const int wid = tid >> 5, lane = tid & 31;
    if (lane == 0) {
        #pragma unroll
        for (int c = 0; c < CLS; ++c) red[c][wid] = acc[c];
    }
    __syncthreads();
    if (tid < CLS) {
        float s = fc_b[tid];
        #pragma unroll
        for (int k = 0; k < 8; ++k) s += red[tid][k];
        out[b * CLS + tid] = s;
    }
}

extern "C" void kernel_launch(void* const* d_in, const int* in_sizes, int n_in,
                              void* d_out, int out_size)
{
    const float* x        = (const float*)d_in[0];
    const float* input_w  = (const float*)d_in[1];
    const float* input_b  = (const float*)d_in[2];
    const float* s_mu     = (const float*)d_in[3];
    const float* s_sigma  = (const float*)d_in[4];
    const float* s_w      = (const float*)d_in[5];
    const float* s_erev   = (const float*)d_in[6];
    const float* mu       = (const float*)d_in[7];
    const float* sigma    = (const float*)d_in[8];
    const float* w        = (const float*)d_in[9];
    const float* erev     = (const float*)d_in[10];
    const float* gleak    = (const float*)d_in[11];
    const float* vleak    = (const float*)d_in[12];
    const float* cm       = (const float*)d_in[13];
    const float* output_w = (const float*)d_in[14];
    const float* output_b = (const float*)d_in[15];
    const float* fc_w     = (const float*)d_in[16];
    const float* fc_b     = (const float*)d_in[17];
    const int*   s_mask   = (const int*)d_in[18];
    const int*   mask     = (const int*)d_in[19];
    float* out = (float*)d_out;

    ltc_kernel<<<B_ / 2, 128>>>(x, input_w, input_b, s_mu, s_sigma, s_w, s_erev,
                                mu, sigma, w, erev, gleak, vleak, cm,
                                output_w, output_b, s_mask, mask);
    fc_kernel<<<B_, 256>>>(fc_w, fc_b, out);
}

// round 16
// speedup vs baseline: 1.4671x; 1.3005x over previous
#include <cuda_runtime.h>

#define B_ 256
#define T_ 2048
#define S_ 32
#define N_ 19
#define UNF 6
#define CLS 10
#define EPSV 1e-8f

// scratch for per-step motor outputs: flat[b][t]  (MOTOR == 1)
__device__ float g_flat[B_ * T_];

__device__ __forceinline__ float tanhf_a(float x) {
    float y; asm("tanh.approx.f32 %0, %1;" : "=f"(y) : "f"(x)); return y;
}
__device__ __forceinline__ float rcpf(float x) {
    float y; asm("rcp.approx.ftz.f32 %0, %1;" : "=f"(y) : "f"(x)); return y;
}

// sigmoid(sg*(v-mu)) = 0.5 + 0.5*tanh(0.5*sg*v - 0.5*sg*mu)
//   constant 0.5*w part folded into per-lane accumulator init (Kns/Knr/...).
//
// One warp per batch. lane = post-neuron (19 live, 13 clamped mirrors).
// Block = 64 threads = 2 warps = 2 independent batches; grid = 128 -> 1 block/SM,
// 2 warps on 2 SMSPs, no barriers anywhere in the 2048-step loop.
__global__ __launch_bounds__(64, 1)
void ltc_kernel(const float* __restrict__ x,
                const float* __restrict__ input_w, const float* __restrict__ input_b,
                const float* __restrict__ s_mu,   const float* __restrict__ s_sigma,
                const float* __restrict__ s_w,    const float* __restrict__ s_erev,
                const float* __restrict__ mu,     const float* __restrict__ sigma,
                const float* __restrict__ w,      const float* __restrict__ erev,
                const float* __restrict__ gleak,  const float* __restrict__ vleak,
                const float* __restrict__ cm,
                const float* __restrict__ out_w,  const float* __restrict__ out_b,
                const int*   __restrict__ s_mask, const int* __restrict__ mask)
{
    // sensory tables: [s][lane] float4 (0.5*sg, -0.5*sg*mu, 0.5*wE, 0.5*wD)
    __shared__ float4 cs[S_ * 32];

    const int tid  = threadIdx.x;
    const int warp = tid >> 5, lane = tid & 31;
    const int b    = blockIdx.x * 2 + warp;
    const int ln   = (lane < N_) ? lane : (N_ - 1);   // clamp: idle lanes mirror neuron 18

    // ---- build sensory table (cooperative, once) ----
    for (int i = tid; i < S_ * 32; i += 64) {
        int s = i >> 5, l = i & 31;
        int n = (l < N_) ? l : (N_ - 1);
        int idx = s * N_ + n;
        float sg = s_sigma[idx];
        float wm = 0.5f * s_w[idx] * (float)s_mask[idx];
        cs[i] = make_float4(0.5f * sg, -0.5f * sg * s_mu[idx], wm * s_erev[idx], wm);
    }
    __syncthreads();

    // ---- recurrent constants live in REGISTERS (compile-time indexed) ----
    float ra[N_], rb[N_], rwe[N_], rwd[N_];
    float Knr = 0.f, Kdr = 0.f;
    #pragma unroll
    for (int j = 0; j < N_; ++j) {
        int idx = j * N_ + ln;
        float sg = sigma[idx];
        float wm = 0.5f * w[idx] * (float)mask[idx];
        ra[j]  = 0.5f * sg;
        rb[j]  = -0.5f * sg * mu[idx];
        rwe[j] = wm * erev[idx];
        rwd[j] = wm;
        Knr += rwe[j];
        Kdr += rwd[j];
    }
    float Kns = 0.f, Kds = 0.f;
    #pragma unroll
    for (int s = 0; s < S_; ++s) {
        float4 c = cs[s * 32 + lane];
        Kns += c.z;
        Kds += c.w;
    }

    const float gl  = gleak[ln];
    const float cmt = cm[ln] * (float)UNF;
    const float Pc  = gl * vleak[ln];
    const float D0  = cmt + gl + EPSV;
    const float ow = out_w[0], ob = out_b[0];
    const float iw = input_w[lane], ib = input_b[lane];   // lane = sensory channel (S==32)

    const float* xb = x + (size_t)b * T_ * S_;
    float inp_next = fmaf(xb[lane], iw, ib);              // prefetch t=0
    float v = 0.f;

    for (int t = 0; t < T_; ++t) {
        float inp = inp_next;
        if (t + 1 < T_) inp_next = fmaf(xb[(t + 1) * S_ + lane], iw, ib);

        // ---- sensory synapses: full fan-in, no exchange needed ----
        float ns = Kns, ds = Kds;
        #pragma unroll
        for (int s = 0; s < S_; ++s) {
            float iv = __shfl_sync(0xffffffffu, inp, s);
            float4 c = cs[s * 32 + lane];
            float tv = tanhf_a(fmaf(c.x, iv, c.y));
            ns = fmaf(c.z, tv, ns);
            ds = fmaf(c.w, tv, ds);
        }

        // ---- 6 ODE unfolds, fully in-warp (rolled loop to stay in I$ L0) ----
        #pragma unroll 1
        for (int u = 0; u < UNF; ++u) {
            float nu = ns + Knr, du = ds + Kdr;
            #pragma unroll
            for (int j = 0; j < N_; ++j) {
                float vj = __shfl_sync(0xffffffffu, v, j);
                float tv = tanhf_a(fmaf(ra[j], vj, rb[j]));
                nu = fmaf(rwe[j], tv, nu);
                du = fmaf(rwd[j], tv, du);
            }
            v = (fmaf(cmt, v, Pc) + nu) * rcpf(D0 + du);
        }

        // motor output (MOTOR==1): neuron 0
        if (lane == 0)
            g_flat[(size_t)b * T_ + t] = fmaf(v, ow, ob);
    }
}

// FC over time: out[b][c] = sum_t flat[b][t] * fc_w[c][t] + fc_b[c]
__global__ __launch_bounds__(256)
void fc_kernel(const float* __restrict__ fc_w, const float* __restrict__ fc_b,
               float* __restrict__ out)
{
    const int b = blockIdx.x, tid = threadIdx.x;
    float acc[CLS];
    #pragma unroll
    for (int c = 0; c < CLS; ++c) acc[c] = 0.f;

    const float* fb = g_flat + (size_t)b * T_;
    for (int t = tid; t < T_; t += 256) {
        float f = fb[t];
        #pragma unroll
        for (int c = 0; c < CLS; ++c)
            acc[c] = fmaf(f, fc_w[c * T_ + t], acc[c]);
    }
    #pragma unroll
    for (int c = 0; c < CLS; ++c)
        #pragma unroll
        for (int off = 16; off; off >>= 1)
            acc[c] += __shfl_down_sync(0xffffffffu, acc[c], off);

    __shared__ float red[CLS][8];
    const int wid = tid >> 5, lane = tid & 31;
    if (lane == 0) {
        #pragma unroll
        for (int c = 0; c < CLS; ++c) red[c][wid] = acc[c];
    }
    __syncthreads();
    if (tid < CLS) {
        float s = fc_b[tid];
        #pragma unroll
        for (int k = 0; k < 8; ++k) s += red[tid][k];
        out[b * CLS + tid] = s;
    }
}

extern "C" void kernel_launch(void* const* d_in, const int* in_sizes, int n_in,
                              void* d_out, int out_size)
{
    const float* x        = (const float*)d_in[0];
    const float* input_w  = (const float*)d_in[1];
    const float* input_b  = (const float*)d_in[2];
    const float* s_mu     = (const float*)d_in[3];
    const float* s_sigma  = (const float*)d_in[4];
    const float* s_w      = (const float*)d_in[5];
    const float* s_erev   = (const float*)d_in[6];
    const float* mu       = (const float*)d_in[7];
    const float* sigma    = (const float*)d_in[8];
    const float* w        = (const float*)d_in[9];
    const float* erev     = (const float*)d_in[10];
    const float* gleak    = (const float*)d_in[11];
    const float* vleak    = (const float*)d_in[12];
    const float* cm       = (const float*)d_in[13];
    const float* output_w = (const float*)d_in[14];
    const float* output_b = (const float*)d_in[15];
    const float* fc_w     = (const float*)d_in[16];
    const float* fc_b     = (const float*)d_in[17];
    const int*   s_mask   = (const int*)d_in[18];
    const int*   mask     = (const int*)d_in[19];
    float* out = (float*)d_out;

    ltc_kernel<<<B_ / 2, 64>>>(x, input_w, input_b, s_mu, s_sigma, s_w, s_erev,
                               mu, sigma, w, erev, gleak, vleak, cm,
                               output_w, output_b, s_mask, mask);
    fc_kernel<<<B_, 256>>>(fc_w, fc_b, out);
}